// round 1
// baseline (speedup 1.0000x reference)
#include <cuda_runtime.h>
#include <math.h>

typedef unsigned long long ull;

#define DM 512
#define TS 4096
#define NB 2
#define NH 8
#define DHD 64
#define BT_ (NB*TS)    // 8192
#define BH_ (NB*NH)    // 16

// ---------------- device scratch (static, allocation-free) ----------------
__device__ float g_Wdq[4][DM*DM];        // dequantized Wq,Wk,Wv,Wo
__device__ float g_q [BH_*TS*DHD];       // (b,h,t,dh)
__device__ float g_k [BH_*TS*DHD];
__device__ float g_v [BH_*TS*DHD];
__device__ float g_kc[BH_*TS*DHD];       // compacted kept keys
__device__ float g_vc[BH_*TS*DHD];
__device__ float g_ctx[BT_*DM];          // (b,t,d)
__device__ int   g_kept[NB*TS];
__device__ int   g_cnt[NB];
__device__ int   g_absmax;               // float bits, >=0

// ---------------- packed f32x2 helpers ----------------
static __device__ __forceinline__ ull pk2(float x, float y){
    ull r; asm("mov.b64 %0, {%1,%2};" : "=l"(r) : "f"(x), "f"(y)); return r;
}
static __device__ __forceinline__ float2 upk2(ull v){
    float2 r; asm("mov.b64 {%0,%1}, %2;" : "=f"(r.x), "=f"(r.y) : "l"(v)); return r;
}
static __device__ __forceinline__ void fma2(ull &d, ull a, ull b){
    asm("fma.rn.f32x2 %0, %1, %2, %0;" : "+l"(d) : "l"(a), "l"(b));
}
static __device__ __forceinline__ void mul2(ull &d, ull a){
    asm("mul.rn.f32x2 %0, %0, %1;" : "+l"(d) : "l"(a));
}

// ---------------- 1. per-row symmetric int8 weight quant-dequant ----------------
__global__ void quant_weights_kernel(const float* __restrict__ Wq, const float* __restrict__ Wk,
                                     const float* __restrict__ Wv, const float* __restrict__ Wo)
{
    int w = blockIdx.y;
    int row = blockIdx.x;
    const float* srcs[4] = {Wq, Wk, Wv, Wo};
    const float* wr = srcs[w] + row*DM;
    float* dst = &g_Wdq[w][row*DM];
    int tid = threadIdx.x; // 128
    if (w==0 && row==0 && tid==0) g_absmax = 0;
    float mx = 0.f;
    for (int i=tid;i<DM;i+=128) mx = fmaxf(mx, fabsf(wr[i]));
    for (int off=16;off;off>>=1) mx = fmaxf(mx, __shfl_xor_sync(0xffffffffu, mx, off));
    __shared__ float sm4[4];
    if ((tid&31)==0) sm4[tid>>5] = mx;
    __syncthreads();
    mx = fmaxf(fmaxf(sm4[0],sm4[1]), fmaxf(sm4[2],sm4[3]));
    float s = fmaxf(__fdiv_rn(mx, 127.0f), 1e-8f);   // bit-exact vs jnp
    for (int i=tid;i<DM;i+=128){
        float qv = rintf(__fdiv_rn(wr[i], s));       // round-half-even == jnp.round
        qv = fminf(fmaxf(qv, -127.f), 127.f);
        dst[i] = qv * s;
    }
}

// ---------------- 2. mask compaction (per batch prefix scan) ----------------
__global__ void compact_kernel(const int* __restrict__ mask)
{
    int b = blockIdx.x;
    const int* m = mask + b*TS;
    __shared__ int part[1024];
    int tid = threadIdx.x; // 1024
    int base = tid*4;
    int f0 = m[base]!=0, f1 = m[base+1]!=0, f2 = m[base+2]!=0, f3 = m[base+3]!=0;
    int s = f0+f1+f2+f3;
    part[tid] = s;
    __syncthreads();
    for (int off=1; off<1024; off<<=1){
        int v = (tid>=off) ? part[tid-off] : 0;
        __syncthreads();
        part[tid] += v;
        __syncthreads();
    }
    int o = part[tid] - s + b*TS;
    if (f0) g_kept[o++] = base;
    if (f1) g_kept[o++] = base+1;
    if (f2) g_kept[o++] = base+2;
    if (f3) g_kept[o++] = base+3;
    if (tid==1023) g_cnt[b] = part[1023];
}

// ---------------- 3. QKV projection GEMM (8192x512 @ 512x512^T) ----------------
__global__ void __launch_bounds__(256) qkv_gemm_kernel(const float* __restrict__ x,
    const float* __restrict__ bq, const float* __restrict__ bk, const float* __restrict__ bv)
{
    int mode = blockIdx.z;
    const float* __restrict__ W = g_Wdq[mode];
    const float* __restrict__ bias = (mode==0)?bq:((mode==1)?bk:bv);
    float* __restrict__ dst = (mode==0)?g_q:((mode==1)?g_k:g_v);
    int rowbase = blockIdx.x*64;
    int nbase   = blockIdx.y*64;
    __shared__ __align__(16) float As[32*65]; // As[kk][m]
    __shared__ __align__(16) float Bs[32*66]; // Bs[kk][n], even stride for 8B loads
    int tid = threadIdx.x;
    int ty = tid>>4, tx = tid&15;
    ull acc[4][2];
    #pragma unroll
    for (int r=0;r<4;r++){ acc[r][0]=0ull; acc[r][1]=0ull; }
    for (int kb=0;kb<DM;kb+=32){
        #pragma unroll
        for (int i=0;i<8;i++){
            int idx = tid + i*256;
            int mm = idx>>5, kk = idx&31;
            As[kk*65+mm] = x[(rowbase+mm)*DM + kb+kk];
            Bs[kk*66+mm] = W[(nbase+mm)*DM + kb+kk];
        }
        __syncthreads();
        #pragma unroll
        for (int kk=0;kk<32;kk++){
            ull b01 = *(const ull*)&Bs[kk*66 + tx*4];
            ull b23 = *(const ull*)&Bs[kk*66 + tx*4 + 2];
            #pragma unroll
            for (int r=0;r<4;r++){
                float a = As[kk*65 + ty*4 + r];
                ull aa = pk2(a,a);
                fma2(acc[r][0], aa, b01);
                fma2(acc[r][1], aa, b23);
            }
        }
        __syncthreads();
    }
    int o0 = nbase + tx*4;
    float b0=bias[o0], b1=bias[o0+1], b2=bias[o0+2], b3=bias[o0+3];
    #pragma unroll
    for (int r=0;r<4;r++){
        int row = rowbase + ty*4 + r;
        int bb = row>>12, t = row&4095;
        float2 v01 = upk2(acc[r][0]);
        float2 v23 = upk2(acc[r][1]);
        float vals[4] = {v01.x+b0, v01.y+b1, v23.x+b2, v23.y+b3};
        #pragma unroll
        for (int c=0;c<4;c++){
            int o = o0+c;
            dst[((bb*NH + (o>>6))*TS + t)*DHD + (o&63)] = vals[c];
        }
    }
}

// ---------------- 4. gather kept K/V into contiguous buffers ----------------
__global__ void gather_kernel()
{
    int idx = blockIdx.x*256 + threadIdx.x;
    int d  = idx & 63;
    int j  = (idx>>6) & (TS-1);
    int bh = idx >> 18;
    int b  = bh >> 3;
    if (j < g_cnt[b]){
        int src = g_kept[b*TS + j];
        int si = (bh*TS + src)*DHD + d;
        g_kc[idx] = g_k[si];
        g_vc[idx] = g_v[si];
    }
}

// ---------------- 5. flash-style attention (BQ=64, BK=32, dh=64) ----------------
__global__ void __launch_bounds__(256) attn_kernel()
{
    int bh = blockIdx.y;
    int b = bh>>3, h = bh&7;
    int qbase = blockIdx.x*64;
    __shared__ __align__(16) float Qs[64*65]; // [d][q]
    __shared__ __align__(16) float Ks[64*34]; // [d][j]
    __shared__ __align__(16) float Vs[32*66]; // [j][d]
    __shared__ __align__(16) float Ss[64*33]; // [q][j]
    __shared__ float m_s[64], l_s[64], c_s[64];
    int tid = threadIdx.x;
    int ty = tid>>4, tx = tid&15;
    #pragma unroll
    for (int i=0;i<16;i++){
        int idx = tid + i*256;
        int q = idx>>6, d = idx&63;
        Qs[d*65+q] = g_q[(bh*TS + qbase + q)*DHD + d] * 0.125f; // 1/sqrt(64)
    }
    if (tid<64){ m_s[tid] = -1e30f; l_s[tid] = 0.f; }
    ull o2[4][2];
    #pragma unroll
    for (int r=0;r<4;r++){ o2[r][0]=0ull; o2[r][1]=0ull; }
    int cnt = g_cnt[b];
    __syncthreads();
    for (int kb=0; kb<cnt; kb+=32){
        #pragma unroll
        for (int i=0;i<8;i++){
            int idx = tid + i*256;
            int j = idx>>6, d = idx&63;
            bool ok = (kb+j) < cnt;
            int gi = (bh*TS + kb + j)*DHD + d;
            float kv = ok ? g_kc[gi] : 0.f;
            float vv = ok ? g_vc[gi] : 0.f;
            Ks[d*34+j] = kv;
            Vs[j*66+d] = vv;
        }
        __syncthreads();
        // S(64x32) = Qs^T @ Ks  (each thread: 4 q-rows x 1 j-pair)
        ull s2[4] = {0ull,0ull,0ull,0ull};
        #pragma unroll 16
        for (int d=0; d<64; d++){
            ull kp = *(const ull*)&Ks[d*34 + tx*2];
            #pragma unroll
            for (int r=0;r<4;r++){
                float a = Qs[d*65 + ty*4 + r];
                fma2(s2[r], pk2(a,a), kp);
            }
        }
        #pragma unroll
        for (int r=0;r<4;r++){
            float2 sv = upk2(s2[r]);
            int q = ty*4 + r;
            int j0 = tx*2;
            Ss[q*33+j0]   = (kb+j0   < cnt) ? sv.x : -1e30f;
            Ss[q*33+j0+1] = (kb+j0+1 < cnt) ? sv.y : -1e30f;
        }
        __syncthreads();
        // online softmax row pass
        if (tid < 64){
            int q = tid;
            float mold = m_s[q];
            float mt = mold;
            float vals[32];
            #pragma unroll
            for (int j=0;j<32;j++){ vals[j] = Ss[q*33+j]; mt = fmaxf(mt, vals[j]); }
            float c = expf(mold - mt);
            float sum = 0.f;
            #pragma unroll
            for (int j=0;j<32;j++){ float p = expf(vals[j]-mt); Ss[q*33+j] = p; sum += p; }
            m_s[q] = mt; c_s[q] = c; l_s[q] = l_s[q]*c + sum;
        }
        __syncthreads();
        // rescale O and accumulate O += P @ V
        #pragma unroll
        for (int r=0;r<4;r++){
            float c = c_s[ty*4+r];
            ull cc = pk2(c,c);
            mul2(o2[r][0], cc);
            mul2(o2[r][1], cc);
        }
        #pragma unroll
        for (int kk=0;kk<32;kk++){
            ull v01 = *(const ull*)&Vs[kk*66 + tx*4];
            ull v23 = *(const ull*)&Vs[kk*66 + tx*4 + 2];
            #pragma unroll
            for (int r=0;r<4;r++){
                float a = Ss[(ty*4+r)*33 + kk];
                ull aa = pk2(a,a);
                fma2(o2[r][0], aa, v01);
                fma2(o2[r][1], aa, v23);
            }
        }
        __syncthreads();
    }
    #pragma unroll
    for (int r=0;r<4;r++){
        int q = ty*4+r;
        float inv = __fdiv_rn(1.0f, l_s[q]);
        float2 v01 = upk2(o2[r][0]);
        float2 v23 = upk2(o2[r][1]);
        int t = qbase + q;
        float* dstp = &g_ctx[(b*TS + t)*DM + h*DHD + tx*4];
        dstp[0] = v01.x*inv; dstp[1] = v01.y*inv;
        dstp[2] = v23.x*inv; dstp[3] = v23.y*inv;
    }
}

// ---------------- 6. output projection + global absmax ----------------
__global__ void __launch_bounds__(256) out_gemm_kernel(const float* __restrict__ bo,
                                                       float* __restrict__ outp)
{
    const float* __restrict__ W = g_Wdq[3];
    const float* __restrict__ x = g_ctx;
    int rowbase = blockIdx.x*64;
    int nbase   = blockIdx.y*64;
    __shared__ __align__(16) float As[32*65];
    __shared__ __align__(16) float Bs[32*66];
    int tid = threadIdx.x;
    int ty = tid>>4, tx = tid&15;
    ull acc[4][2];
    #pragma unroll
    for (int r=0;r<4;r++){ acc[r][0]=0ull; acc[r][1]=0ull; }
    for (int kb=0;kb<DM;kb+=32){
        #pragma unroll
        for (int i=0;i<8;i++){
            int idx = tid + i*256;
            int mm = idx>>5, kk = idx&31;
            As[kk*65+mm] = x[(rowbase+mm)*DM + kb+kk];
            Bs[kk*66+mm] = W[(nbase+mm)*DM + kb+kk];
        }
        __syncthreads();
        #pragma unroll
        for (int kk=0;kk<32;kk++){
            ull b01 = *(const ull*)&Bs[kk*66 + tx*4];
            ull b23 = *(const ull*)&Bs[kk*66 + tx*4 + 2];
            #pragma unroll
            for (int r=0;r<4;r++){
                float a = As[kk*65 + ty*4 + r];
                ull aa = pk2(a,a);
                fma2(acc[r][0], aa, b01);
                fma2(acc[r][1], aa, b23);
            }
        }
        __syncthreads();
    }
    int o0 = nbase + tx*4;
    float b0=bo[o0], b1=bo[o0+1], b2=bo[o0+2], b3=bo[o0+3];
    float amax = 0.f;
    #pragma unroll
    for (int r=0;r<4;r++){
        int row = rowbase + ty*4 + r;
        float2 v01 = upk2(acc[r][0]);
        float2 v23 = upk2(acc[r][1]);
        float vals[4] = {v01.x+b0, v01.y+b1, v23.x+b2, v23.y+b3};
        #pragma unroll
        for (int c=0;c<4;c++){
            outp[row*DM + o0 + c] = vals[c];
            amax = fmaxf(amax, fabsf(vals[c]));
        }
    }
    for (int off=16;off;off>>=1) amax = fmaxf(amax, __shfl_xor_sync(0xffffffffu, amax, off));
    __shared__ float red[8];
    if ((tid&31)==0) red[tid>>5] = amax;
    __syncthreads();
    if (tid==0){
        float m = red[0];
        #pragma unroll
        for (int i=1;i<8;i++) m = fmaxf(m, red[i]);
        atomicMax(&g_absmax, __float_as_int(m)); // vals >= 0: int compare == float compare
    }
}

// ---------------- 7. final per-tensor int8 quant-dequant ----------------
__global__ void quant_out_kernel(float* __restrict__ outp)
{
    float s = fmaxf(__fdiv_rn(__int_as_float(g_absmax), 127.0f), 1e-8f);
    int i = blockIdx.x*256 + threadIdx.x;
    float v = outp[i];
    float qv = rintf(__fdiv_rn(v, s));
    qv = fminf(fmaxf(qv, -127.f), 127.f);
    outp[i] = qv * s;
}

// ---------------- launch ----------------
extern "C" void kernel_launch(void* const* d_in, const int* in_sizes, int n_in,
                              void* d_out, int out_size)
{
    (void)in_sizes; (void)n_in; (void)out_size;
    const float* x  = (const float*)d_in[0];
    const int*   mk = (const int*)  d_in[1];
    const float* Wq = (const float*)d_in[2];
    const float* bq = (const float*)d_in[3];
    const float* Wk = (const float*)d_in[4];
    const float* bk = (const float*)d_in[5];
    const float* Wv = (const float*)d_in[6];
    const float* bv = (const float*)d_in[7];
    const float* Wo = (const float*)d_in[8];
    const float* bo = (const float*)d_in[9];
    float* outp = (float*)d_out;

    quant_weights_kernel<<<dim3(DM,4), 128>>>(Wq,Wk,Wv,Wo);
    compact_kernel<<<NB, 1024>>>(mk);
    qkv_gemm_kernel<<<dim3(BT_/64, DM/64, 3), 256>>>(x, bq, bk, bv);
    gather_kernel<<<(BH_*TS*DHD)/256, 256>>>();
    attn_kernel<<<dim3(TS/64, BH_), 256>>>();
    out_gemm_kernel<<<dim3(BT_/64, DM/64), 256>>>(bo, outp);
    quant_out_kernel<<<(BT_*DM)/256, 256>>>(outp);
}

// round 8
// speedup vs baseline: 1.3010x; 1.3010x over previous
#include <cuda_runtime.h>
#include <cuda_bf16.h>
#include <math.h>
#include <stdint.h>

typedef unsigned long long ull;

#define DM 512
#define TS 4096
#define NB 2
#define NH 8
#define DHD 64
#define BT_ (NB*TS)    // 8192
#define BH_ (NB*NH)    // 16

// ---------------- device scratch (static, allocation-free) ----------------
// NOTE: these symbols are ONLY referenced inside device code. Passing a
// __device__ symbol as a kernel argument from host silently yields the host
// shadow address (writable via ATS on GB300!) — that was the R4-R7 bug.
__device__ __nv_bfloat16 g_Wb[4][DM*DM];   // integer-valued quantized weights (exact in bf16)
__device__ float g_ws[4][DM];              // per-output-row scales
__device__ __nv_bfloat16 g_xhi[BT_*DM];    // bf16 hi/lo split of x
__device__ __nv_bfloat16 g_xlo[BT_*DM];
__device__ __nv_bfloat16 g_chi[BT_*DM];    // bf16 hi/lo split of ctx
__device__ __nv_bfloat16 g_clo[BT_*DM];
__device__ float g_q [BH_*TS*DHD];         // (b,h,t,dh) fp32
__device__ float g_k [BH_*TS*DHD];
__device__ float g_v [BH_*TS*DHD];
__device__ float g_kc[BH_*TS*DHD];         // compacted kept keys (fp32)
__device__ float g_vc[BH_*TS*DHD];
__device__ float g_ctx[BT_*DM];            // (b,t,d) fp32
__device__ int   g_kept[NB*TS];
__device__ int   g_cnt[NB];
__device__ int   g_absmax;                 // float bits, >=0

// ---------------- packed f32x2 helpers (SIMT attention) ----------------
static __device__ __forceinline__ ull pk2(float x, float y){
    ull r; asm("mov.b64 %0, {%1,%2};" : "=l"(r) : "f"(x), "f"(y)); return r;
}
static __device__ __forceinline__ float2 upk2(ull v){
    float2 r; asm("mov.b64 {%0,%1}, %2;" : "=f"(r.x), "=f"(r.y) : "l"(v)); return r;
}
static __device__ __forceinline__ void fma2(ull &d, ull a, ull b){
    asm("fma.rn.f32x2 %0, %1, %2, %0;" : "+l"(d) : "l"(a), "l"(b));
}
static __device__ __forceinline__ void mul2(ull &d, ull a){
    asm("mul.rn.f32x2 %0, %0, %1;" : "+l"(d) : "l"(a));
}

// ---------------- mma helper (sm_80-level, arch-portable) ----------------
static __device__ __forceinline__ void mma16816(float* d, const uint32_t* a, const uint32_t* b){
    asm volatile("mma.sync.aligned.m16n8k16.row.col.f32.bf16.bf16.f32 "
        "{%0,%1,%2,%3}, {%4,%5,%6,%7}, {%8,%9}, {%0,%1,%2,%3};"
        : "+f"(d[0]),"+f"(d[1]),"+f"(d[2]),"+f"(d[3])
        : "r"(a[0]),"r"(a[1]),"r"(a[2]),"r"(a[3]), "r"(b[0]),"r"(b[1]));
}
static __device__ __forceinline__ uint32_t lds32(const __nv_bfloat16* p){
    return *(const uint32_t*)p;   // aligned bf16 pair
}

// ---------------- 1. per-row symmetric int8 weight quant (bf16 ints + scales) ----------------
__global__ void quant_weights_kernel(const float* __restrict__ Wq, const float* __restrict__ Wk,
                                     const float* __restrict__ Wv, const float* __restrict__ Wo)
{
    int w = blockIdx.y;
    int row = blockIdx.x;
    const float* srcs[4] = {Wq, Wk, Wv, Wo};
    const float* wr = srcs[w] + row*DM;
    __nv_bfloat16* dst = &g_Wb[w][row*DM];
    int tid = threadIdx.x; // 128
    if (w==0 && row==0 && tid==0) g_absmax = 0;
    float mx = 0.f;
    for (int i=tid;i<DM;i+=128) mx = fmaxf(mx, fabsf(wr[i]));
    for (int off=16;off;off>>=1) mx = fmaxf(mx, __shfl_xor_sync(0xffffffffu, mx, off));
    __shared__ float sm4[4];
    if ((tid&31)==0) sm4[tid>>5] = mx;
    __syncthreads();
    mx = fmaxf(fmaxf(sm4[0],sm4[1]), fmaxf(sm4[2],sm4[3]));
    float s = fmaxf(__fdiv_rn(mx, 127.0f), 1e-8f);
    if (tid==0) g_ws[w][row] = s;
    for (int i=tid;i<DM;i+=128){
        float qv = rintf(__fdiv_rn(wr[i], s));       // round-half-even == jnp.round
        qv = fminf(fmaxf(qv, -127.f), 127.f);
        dst[i] = __float2bfloat16(qv);               // integer <=127: exact in bf16
    }
}

// ---------------- 1b. bf16 hi/lo split (globals referenced IN-KERNEL only) ----------------
__global__ void split_kernel(const float* __restrict__ xin, int mode)
{
    const float* src = (mode==0) ? xin : g_ctx;
    __nv_bfloat16* hi = (mode==0) ? g_xhi : g_chi;
    __nv_bfloat16* lo = (mode==0) ? g_xlo : g_clo;
    int i = (blockIdx.x*256 + threadIdx.x)*4;
    float4 v = *(const float4*)&src[i];
    __nv_bfloat16 h0=__float2bfloat16(v.x), h1=__float2bfloat16(v.y);
    __nv_bfloat16 h2=__float2bfloat16(v.z), h3=__float2bfloat16(v.w);
    __nv_bfloat162 hA; hA.x=h0; hA.y=h1;
    __nv_bfloat162 hB; hB.x=h2; hB.y=h3;
    __nv_bfloat162 lA; lA.x=__float2bfloat16(v.x-__bfloat162float(h0)); lA.y=__float2bfloat16(v.y-__bfloat162float(h1));
    __nv_bfloat162 lB; lB.x=__float2bfloat16(v.z-__bfloat162float(h2)); lB.y=__float2bfloat16(v.w-__bfloat162float(h3));
    *(__nv_bfloat162*)&hi[i]   = hA;
    *(__nv_bfloat162*)&hi[i+2] = hB;
    *(__nv_bfloat162*)&lo[i]   = lA;
    *(__nv_bfloat162*)&lo[i+2] = lB;
}

// ---------------- 2. mask compaction (per batch prefix scan) ----------------
__global__ void compact_kernel(const int* __restrict__ mask)
{
    int b = blockIdx.x;
    const int* m = mask + b*TS;
    __shared__ int part[1024];
    int tid = threadIdx.x; // 1024
    int base = tid*4;
    int f0 = m[base]!=0, f1 = m[base+1]!=0, f2 = m[base+2]!=0, f3 = m[base+3]!=0;
    int s = f0+f1+f2+f3;
    part[tid] = s;
    __syncthreads();
    for (int off=1; off<1024; off<<=1){
        int v = (tid>=off) ? part[tid-off] : 0;
        __syncthreads();
        part[tid] += v;
        __syncthreads();
    }
    int o = part[tid] - s + b*TS;
    if (f0) g_kept[o++] = base;
    if (f1) g_kept[o++] = base+1;
    if (f2) g_kept[o++] = base+2;
    if (f3) g_kept[o++] = base+3;
    if (tid==1023) g_cnt[b] = part[1023];
}

// ---------------- 3. mma GEMM, direct-LDS fragments: out = (Ahi+Alo) @ Wb^T * s[n] + bias[n] ----
// Block 128x128, BK=32, 256 threads = 8 warps (4 in M x 2 in N), warp tile 32x64.
// Fragment coords per PTX ISA (g = lane>>2, t = lane&3):
//   a0=(g,2t) a1=(g+8,2t) a2=(g,2t+8) a3=(g+8,2t+8)   [A row-major m16k16]
//   b0=(k=2t..2t+1, n=g)  b1=(k+8, n=g)               [B col-major == sB[n][k]]
//   c0,c1=(g, 2t..2t+1)   c2,c3=(g+8, 2t..2t+1)
#define SKA 40
__global__ void __launch_bounds__(256) gemm_mma_kernel(
    const float* __restrict__ bq, const float* __restrict__ bk,
    const float* __restrict__ bv, const float* __restrict__ bo,
    float* __restrict__ outp, int modebase)
{
    __shared__ __align__(16) __nv_bfloat16 sA[2][128][SKA];
    __shared__ __align__(16) __nv_bfloat16 sB[128][SKA];
    __shared__ float s_sc[128], s_bi[128];
    __shared__ float red8[8];
    int mode = modebase + blockIdx.z;
    int tid = threadIdx.x, lane = tid&31, wid = tid>>5;
    int wm = wid>>1, wn = wid&1;
    int g = lane>>2, t = lane&3;
    int rowbase = blockIdx.x*128, nbase = blockIdx.y*128;

    const __nv_bfloat16* __restrict__ Ahi = (mode<3) ? g_xhi : g_chi;
    const __nv_bfloat16* __restrict__ Alo = (mode<3) ? g_xlo : g_clo;
    const __nv_bfloat16* __restrict__ Bw  = g_Wb[mode];
    const float* biasp = (mode==0)?bq:((mode==1)?bk:((mode==2)?bv:bo));
    if (tid<128) s_sc[tid] = g_ws[mode][nbase+tid];
    else         s_bi[tid-128] = biasp[nbase+tid-128];

    float acc[2][8][4];
    #pragma unroll
    for (int mt=0;mt<2;mt++)
      #pragma unroll
      for (int nt=0;nt<8;nt++)
        #pragma unroll
        for (int c=0;c<4;c++) acc[mt][nt][c] = 0.f;

    for (int kb=0; kb<DM; kb+=32){
        #pragma unroll
        for (int i=0;i<2;i++){
            int id = tid + i*256;   // 0..511
            int r = id>>2, c = id&3;
            *(uint4*)&sA[0][r][c*8] = *(const uint4*)&Ahi[(rowbase+r)*DM + kb + c*8];
            *(uint4*)&sA[1][r][c*8] = *(const uint4*)&Alo[(rowbase+r)*DM + kb + c*8];
            *(uint4*)&sB[r][c*8]    = *(const uint4*)&Bw [(nbase  +r)*DM + kb + c*8];
        }
        __syncthreads();
        #pragma unroll
        for (int ks=0; ks<32; ks+=16){
            uint32_t af[2][2][4];
            #pragma unroll
            for (int h=0; h<2; h++)
              #pragma unroll
              for (int mt=0; mt<2; mt++){
                int r0 = wm*32 + mt*16;
                af[h][mt][0] = lds32(&sA[h][r0 + g    ][ks + 2*t    ]);
                af[h][mt][1] = lds32(&sA[h][r0 + g + 8][ks + 2*t    ]);
                af[h][mt][2] = lds32(&sA[h][r0 + g    ][ks + 2*t + 8]);
                af[h][mt][3] = lds32(&sA[h][r0 + g + 8][ks + 2*t + 8]);
              }
            #pragma unroll
            for (int np=0; np<8; np++){
                int n0 = wn*64 + np*8;
                uint32_t bf2[2];
                bf2[0] = lds32(&sB[n0 + g][ks + 2*t    ]);
                bf2[1] = lds32(&sB[n0 + g][ks + 2*t + 8]);
                #pragma unroll
                for (int mt=0; mt<2; mt++){
                    mma16816(acc[mt][np], af[0][mt], bf2);
                    mma16816(acc[mt][np], af[1][mt], bf2);
                }
            }
        }
        __syncthreads();
    }
    // epilogue
    float amax = 0.f;
    float* qkv = (mode==0)?g_q:((mode==1)?g_k:g_v);
    #pragma unroll
    for (int mt=0;mt<2;mt++){
      #pragma unroll
      for (int nt=0;nt<8;nt++){
        int ncol = wn*64 + nt*8 + 2*t;
        float s0 = s_sc[ncol], s1 = s_sc[ncol+1];
        float b0 = s_bi[ncol], b1 = s_bi[ncol+1];
        #pragma unroll
        for (int rh=0; rh<2; rh++){
            int row = rowbase + wm*32 + mt*16 + g + rh*8;
            float v0 = acc[mt][nt][rh*2  ]*s0 + b0;
            float v1 = acc[mt][nt][rh*2+1]*s1 + b1;
            float2 w; w.x = v0; w.y = v1;
            if (mode<3){
                int o = nbase + ncol;
                int head = o>>6, dh = o&63;
                int bb = row>>12, tt = row&4095;
                *(float2*)&qkv[((bb*NH+head)*TS + tt)*DHD + dh] = w;
            } else {
                *(float2*)&outp[row*DM + nbase + ncol] = w;
                amax = fmaxf(amax, fmaxf(fabsf(v0), fabsf(v1)));
            }
        }
      }
    }
    if (mode==3){
        for (int off=16;off;off>>=1) amax = fmaxf(amax, __shfl_xor_sync(0xffffffffu, amax, off));
        if (lane==0) red8[wid] = amax;
        __syncthreads();
        if (tid==0){
            float m = red8[0];
            #pragma unroll
            for (int i=1;i<8;i++) m = fmaxf(m, red8[i]);
            atomicMax(&g_absmax, __float_as_int(m));
        }
    }
}

// ---------------- 4. gather kept K/V into contiguous fp32 buffers (R1, proven) ----------------
__global__ void gather_kernel()
{
    int idx = blockIdx.x*256 + threadIdx.x;
    int d  = idx & 63;
    int j  = (idx>>6) & (TS-1);
    int bh = idx >> 18;
    int b  = bh >> 3;
    if (j < g_cnt[b]){
        int src = g_kept[b*TS + j];
        int si = (bh*TS + src)*DHD + d;
        g_kc[idx] = g_k[si];
        g_vc[idx] = g_v[si];
    }
}

// ---------------- 5. flash-style SIMT attention (R1, proven) ----------------
__global__ void __launch_bounds__(256) attn_kernel()
{
    int bh = blockIdx.y;
    int b = bh>>3, h = bh&7;
    int qbase = blockIdx.x*64;
    __shared__ __align__(16) float Qs[64*65]; // [d][q]
    __shared__ __align__(16) float Ks[64*34]; // [d][j]
    __shared__ __align__(16) float Vs[32*66]; // [j][d]
    __shared__ __align__(16) float Ss[64*33]; // [q][j]
    __shared__ float m_s[64], l_s[64], c_s[64];
    int tid = threadIdx.x;
    int ty = tid>>4, tx = tid&15;
    #pragma unroll
    for (int i=0;i<16;i++){
        int idx = tid + i*256;
        int q = idx>>6, d = idx&63;
        Qs[d*65+q] = g_q[(bh*TS + qbase + q)*DHD + d] * 0.125f; // 1/sqrt(64)
    }
    if (tid<64){ m_s[tid] = -1e30f; l_s[tid] = 0.f; }
    ull o2[4][2];
    #pragma unroll
    for (int r=0;r<4;r++){ o2[r][0]=0ull; o2[r][1]=0ull; }
    int cnt = g_cnt[b];
    __syncthreads();
    for (int kb=0; kb<cnt; kb+=32){
        #pragma unroll
        for (int i=0;i<8;i++){
            int idx = tid + i*256;
            int j = idx>>6, d = idx&63;
            bool ok = (kb+j) < cnt;
            int gi = (bh*TS + kb + j)*DHD + d;
            float kv = ok ? g_kc[gi] : 0.f;
            float vv = ok ? g_vc[gi] : 0.f;
            Ks[d*34+j] = kv;
            Vs[j*66+d] = vv;
        }
        __syncthreads();
        ull s2[4] = {0ull,0ull,0ull,0ull};
        #pragma unroll 16
        for (int d=0; d<64; d++){
            ull kp = *(const ull*)&Ks[d*34 + tx*2];
            #pragma unroll
            for (int r=0;r<4;r++){
                float a = Qs[d*65 + ty*4 + r];
                fma2(s2[r], pk2(a,a), kp);
            }
        }
        #pragma unroll
        for (int r=0;r<4;r++){
            float2 sv = upk2(s2[r]);
            int q = ty*4 + r;
            int j0 = tx*2;
            Ss[q*33+j0]   = (kb+j0   < cnt) ? sv.x : -1e30f;
            Ss[q*33+j0+1] = (kb+j0+1 < cnt) ? sv.y : -1e30f;
        }
        __syncthreads();
        if (tid < 64){
            int q = tid;
            float mold = m_s[q];
            float mt = mold;
            float vals[32];
            #pragma unroll
            for (int j=0;j<32;j++){ vals[j] = Ss[q*33+j]; mt = fmaxf(mt, vals[j]); }
            float c = expf(mold - mt);
            float sum = 0.f;
            #pragma unroll
            for (int j=0;j<32;j++){ float p = expf(vals[j]-mt); Ss[q*33+j] = p; sum += p; }
            m_s[q] = mt; c_s[q] = c; l_s[q] = l_s[q]*c + sum;
        }
        __syncthreads();
        #pragma unroll
        for (int r=0;r<4;r++){
            float c = c_s[ty*4+r];
            ull cc = pk2(c,c);
            mul2(o2[r][0], cc);
            mul2(o2[r][1], cc);
        }
        #pragma unroll
        for (int kk=0;kk<32;kk++){
            ull v01 = *(const ull*)&Vs[kk*66 + tx*4];
            ull v23 = *(const ull*)&Vs[kk*66 + tx*4 + 2];
            #pragma unroll
            for (int r=0;r<4;r++){
                float a = Ss[(ty*4+r)*33 + kk];
                ull aa = pk2(a,a);
                fma2(o2[r][0], aa, v01);
                fma2(o2[r][1], aa, v23);
            }
        }
        __syncthreads();
    }
    #pragma unroll
    for (int r=0;r<4;r++){
        int q = ty*4+r;
        float inv = __fdiv_rn(1.0f, l_s[q]);
        float2 v01 = upk2(o2[r][0]);
        float2 v23 = upk2(o2[r][1]);
        int t = qbase + q;
        float* dstp = &g_ctx[(b*TS + t)*DM + h*DHD + tx*4];
        dstp[0] = v01.x*inv; dstp[1] = v01.y*inv;
        dstp[2] = v23.x*inv; dstp[3] = v23.y*inv;
    }
}

// ---------------- 7. final per-tensor int8 quant-dequant ----------------
__global__ void quant_out_kernel(float* __restrict__ outp)
{
    float s = fmaxf(__fdiv_rn(__int_as_float(g_absmax), 127.0f), 1e-8f);
    int i = blockIdx.x*256 + threadIdx.x;
    float v = outp[i];
    float qv = rintf(__fdiv_rn(v, s));
    qv = fminf(fmaxf(qv, -127.f), 127.f);
    outp[i] = qv * s;
}

// ---------------- launch ----------------
extern "C" void kernel_launch(void* const* d_in, const int* in_sizes, int n_in,
                              void* d_out, int out_size)
{
    (void)in_sizes; (void)n_in; (void)out_size;
    const float* x  = (const float*)d_in[0];
    const int*   mk = (const int*)  d_in[1];
    const float* Wq = (const float*)d_in[2];
    const float* bq = (const float*)d_in[3];
    const float* Wk = (const float*)d_in[4];
    const float* bk = (const float*)d_in[5];
    const float* Wv = (const float*)d_in[6];
    const float* bv = (const float*)d_in[7];
    const float* Wo = (const float*)d_in[8];
    const float* bo = (const float*)d_in[9];
    float* outp = (float*)d_out;

    quant_weights_kernel<<<dim3(DM,4), 128>>>(Wq,Wk,Wv,Wo);
    split_kernel<<<(BT_*DM)/1024, 256>>>(x, 0);
    compact_kernel<<<NB, 1024>>>(mk);
    gemm_mma_kernel<<<dim3(BT_/128, DM/128, 3), 256>>>(bq,bk,bv,bo, outp, 0);
    gather_kernel<<<(BH_*TS*DHD)/256, 256>>>();
    attn_kernel<<<dim3(TS/64, BH_), 256>>>();
    split_kernel<<<(BT_*DM)/1024, 256>>>(x, 1);
    gemm_mma_kernel<<<dim3(BT_/128, DM/128, 1), 256>>>(bq,bk,bv,bo, outp, 3);
    quant_out_kernel<<<(BT_*DM)/256, 256>>>(outp);
}

// round 9
// speedup vs baseline: 2.5417x; 1.9538x over previous
#include <cuda_runtime.h>
#include <cuda_bf16.h>
#include <math.h>
#include <stdint.h>

typedef unsigned long long ull;

#define DM 512
#define TS 4096
#define NB 2
#define NH 8
#define DHD 64
#define BT_ (NB*TS)    // 8192
#define BH_ (NB*NH)    // 16

// ---------------- device scratch (static, allocation-free) ----------------
// RULE (root cause of R4-R7 failures): these symbols are referenced ONLY
// inside device code. Never pass a __device__ symbol as a kernel argument.
__device__ __nv_bfloat16 g_Wb[4][DM*DM];   // integer-valued quantized weights (exact in bf16)
__device__ float g_ws[4][DM];              // per-output-row scales
__device__ __nv_bfloat16 g_xhi[BT_*DM];    // bf16 hi/lo split of x
__device__ __nv_bfloat16 g_xlo[BT_*DM];
__device__ __nv_bfloat16 g_chi[BT_*DM];    // bf16 hi/lo split of ctx (written by attention)
__device__ __nv_bfloat16 g_clo[BT_*DM];
__device__ float g_q [BH_*TS*DHD];         // (b,h,t,dh) fp32
__device__ float g_k [BH_*TS*DHD];
__device__ float g_v [BH_*TS*DHD];
__device__ __nv_bfloat16 g_kchi[BH_*TS*DHD];  // compacted K, [bh][j][d] bf16 hi/lo
__device__ __nv_bfloat16 g_kclo[BH_*TS*DHD];
__device__ __nv_bfloat16 g_vchi[BH_*DHD*TS];  // compacted V TRANSPOSED, [bh][d][j]
__device__ __nv_bfloat16 g_vclo[BH_*DHD*TS];
__device__ int   g_kept[NB*TS];
__device__ int   g_cnt[NB];
__device__ int   g_absmax;                 // float bits, >=0

// ---------------- mma helpers (sm_80-level, arch-portable; validated R8) ----------------
static __device__ __forceinline__ void mma16816(float* d, const uint32_t* a, const uint32_t* b){
    asm volatile("mma.sync.aligned.m16n8k16.row.col.f32.bf16.bf16.f32 "
        "{%0,%1,%2,%3}, {%4,%5,%6,%7}, {%8,%9}, {%0,%1,%2,%3};"
        : "+f"(d[0]),"+f"(d[1]),"+f"(d[2]),"+f"(d[3])
        : "r"(a[0]),"r"(a[1]),"r"(a[2]),"r"(a[3]), "r"(b[0]),"r"(b[1]));
}
static __device__ __forceinline__ uint32_t lds32(const void* p){
    return *(const uint32_t*)p;   // aligned bf16 pair
}
// pack (x -> low half, y -> high half) as bf16x2
static __device__ __forceinline__ uint32_t pkbf(float x, float y){
    uint32_t r; asm("cvt.rn.bf16x2.f32 %0, %1, %2;" : "=r"(r) : "f"(y), "f"(x)); return r;
}

// ---------------- 1. per-row symmetric int8 weight quant (bf16 ints + scales) ----------------
__global__ void quant_weights_kernel(const float* __restrict__ Wq, const float* __restrict__ Wk,
                                     const float* __restrict__ Wv, const float* __restrict__ Wo)
{
    int w = blockIdx.y;
    int row = blockIdx.x;
    const float* srcs[4] = {Wq, Wk, Wv, Wo};
    const float* wr = srcs[w] + row*DM;
    __nv_bfloat16* dst = &g_Wb[w][row*DM];
    int tid = threadIdx.x; // 128
    if (w==0 && row==0 && tid==0) g_absmax = 0;
    float mx = 0.f;
    for (int i=tid;i<DM;i+=128) mx = fmaxf(mx, fabsf(wr[i]));
    for (int off=16;off;off>>=1) mx = fmaxf(mx, __shfl_xor_sync(0xffffffffu, mx, off));
    __shared__ float sm4[4];
    if ((tid&31)==0) sm4[tid>>5] = mx;
    __syncthreads();
    mx = fmaxf(fmaxf(sm4[0],sm4[1]), fmaxf(sm4[2],sm4[3]));
    float s = fmaxf(__fdiv_rn(mx, 127.0f), 1e-8f);
    if (tid==0) g_ws[w][row] = s;
    for (int i=tid;i<DM;i+=128){
        float qv = rintf(__fdiv_rn(wr[i], s));       // round-half-even == jnp.round
        qv = fminf(fmaxf(qv, -127.f), 127.f);
        dst[i] = __float2bfloat16(qv);               // integer <=127: exact in bf16
    }
}

// ---------------- 1b. bf16 hi/lo split of x ----------------
__global__ void split_x_kernel(const float* __restrict__ src)
{
    int i = (blockIdx.x*256 + threadIdx.x)*4;
    float4 v = *(const float4*)&src[i];
    __nv_bfloat16 h0=__float2bfloat16(v.x), h1=__float2bfloat16(v.y);
    __nv_bfloat16 h2=__float2bfloat16(v.z), h3=__float2bfloat16(v.w);
    __nv_bfloat162 hA; hA.x=h0; hA.y=h1;
    __nv_bfloat162 hB; hB.x=h2; hB.y=h3;
    __nv_bfloat162 lA; lA.x=__float2bfloat16(v.x-__bfloat162float(h0)); lA.y=__float2bfloat16(v.y-__bfloat162float(h1));
    __nv_bfloat162 lB; lB.x=__float2bfloat16(v.z-__bfloat162float(h2)); lB.y=__float2bfloat16(v.w-__bfloat162float(h3));
    *(__nv_bfloat162*)&g_xhi[i]   = hA;
    *(__nv_bfloat162*)&g_xhi[i+2] = hB;
    *(__nv_bfloat162*)&g_xlo[i]   = lA;
    *(__nv_bfloat162*)&g_xlo[i+2] = lB;
}

// ---------------- 2. mask compaction (per batch prefix scan) ----------------
__global__ void compact_kernel(const int* __restrict__ mask)
{
    int b = blockIdx.x;
    const int* m = mask + b*TS;
    __shared__ int part[1024];
    int tid = threadIdx.x; // 1024
    int base = tid*4;
    int f0 = m[base]!=0, f1 = m[base+1]!=0, f2 = m[base+2]!=0, f3 = m[base+3]!=0;
    int s = f0+f1+f2+f3;
    part[tid] = s;
    __syncthreads();
    for (int off=1; off<1024; off<<=1){
        int v = (tid>=off) ? part[tid-off] : 0;
        __syncthreads();
        part[tid] += v;
        __syncthreads();
    }
    int o = part[tid] - s + b*TS;
    if (f0) g_kept[o++] = base;
    if (f1) g_kept[o++] = base+1;
    if (f2) g_kept[o++] = base+2;
    if (f3) g_kept[o++] = base+3;
    if (tid==1023) g_cnt[b] = part[1023];
}

// ---------------- 3. mma GEMM (validated R8): out = (Ahi+Alo) @ Wb^T * s[n] + bias[n] ----------
#define SKA 40
__global__ void __launch_bounds__(256) gemm_mma_kernel(
    const float* __restrict__ bq, const float* __restrict__ bk,
    const float* __restrict__ bv, const float* __restrict__ bo,
    float* __restrict__ outp, int modebase)
{
    __shared__ __align__(16) __nv_bfloat16 sA[2][128][SKA];
    __shared__ __align__(16) __nv_bfloat16 sB[128][SKA];
    __shared__ float s_sc[128], s_bi[128];
    __shared__ float red8[8];
    int mode = modebase + blockIdx.z;
    int tid = threadIdx.x, lane = tid&31, wid = tid>>5;
    int wm = wid>>1, wn = wid&1;
    int g = lane>>2, t = lane&3;
    int rowbase = blockIdx.x*128, nbase = blockIdx.y*128;

    const __nv_bfloat16* __restrict__ Ahi = (mode<3) ? g_xhi : g_chi;
    const __nv_bfloat16* __restrict__ Alo = (mode<3) ? g_xlo : g_clo;
    const __nv_bfloat16* __restrict__ Bw  = g_Wb[mode];
    const float* biasp = (mode==0)?bq:((mode==1)?bk:((mode==2)?bv:bo));
    if (tid<128) s_sc[tid] = g_ws[mode][nbase+tid];
    else         s_bi[tid-128] = biasp[nbase+tid-128];

    float acc[2][8][4];
    #pragma unroll
    for (int mt=0;mt<2;mt++)
      #pragma unroll
      for (int nt=0;nt<8;nt++)
        #pragma unroll
        for (int c=0;c<4;c++) acc[mt][nt][c] = 0.f;

    for (int kb=0; kb<DM; kb+=32){
        #pragma unroll
        for (int i=0;i<2;i++){
            int id = tid + i*256;   // 0..511
            int r = id>>2, c = id&3;
            *(uint4*)&sA[0][r][c*8] = *(const uint4*)&Ahi[(rowbase+r)*DM + kb + c*8];
            *(uint4*)&sA[1][r][c*8] = *(const uint4*)&Alo[(rowbase+r)*DM + kb + c*8];
            *(uint4*)&sB[r][c*8]    = *(const uint4*)&Bw [(nbase  +r)*DM + kb + c*8];
        }
        __syncthreads();
        #pragma unroll
        for (int ks=0; ks<32; ks+=16){
            uint32_t af[2][2][4];
            #pragma unroll
            for (int h=0; h<2; h++)
              #pragma unroll
              for (int mt=0; mt<2; mt++){
                int r0 = wm*32 + mt*16;
                af[h][mt][0] = lds32(&sA[h][r0 + g    ][ks + 2*t    ]);
                af[h][mt][1] = lds32(&sA[h][r0 + g + 8][ks + 2*t    ]);
                af[h][mt][2] = lds32(&sA[h][r0 + g    ][ks + 2*t + 8]);
                af[h][mt][3] = lds32(&sA[h][r0 + g + 8][ks + 2*t + 8]);
              }
            #pragma unroll
            for (int np=0; np<8; np++){
                int n0 = wn*64 + np*8;
                uint32_t bf2[2];
                bf2[0] = lds32(&sB[n0 + g][ks + 2*t    ]);
                bf2[1] = lds32(&sB[n0 + g][ks + 2*t + 8]);
                #pragma unroll
                for (int mt=0; mt<2; mt++){
                    mma16816(acc[mt][np], af[0][mt], bf2);
                    mma16816(acc[mt][np], af[1][mt], bf2);
                }
            }
        }
        __syncthreads();
    }
    float amax = 0.f;
    float* qkv = (mode==0)?g_q:((mode==1)?g_k:g_v);
    #pragma unroll
    for (int mt=0;mt<2;mt++){
      #pragma unroll
      for (int nt=0;nt<8;nt++){
        int ncol = wn*64 + nt*8 + 2*t;
        float s0 = s_sc[ncol], s1 = s_sc[ncol+1];
        float b0 = s_bi[ncol], b1 = s_bi[ncol+1];
        #pragma unroll
        for (int rh=0; rh<2; rh++){
            int row = rowbase + wm*32 + mt*16 + g + rh*8;
            float v0 = acc[mt][nt][rh*2  ]*s0 + b0;
            float v1 = acc[mt][nt][rh*2+1]*s1 + b1;
            float2 w; w.x = v0; w.y = v1;
            if (mode<3){
                int o = nbase + ncol;
                int head = o>>6, dh = o&63;
                int bb = row>>12, tt = row&4095;
                *(float2*)&qkv[((bb*NH+head)*TS + tt)*DHD + dh] = w;
            } else {
                *(float2*)&outp[row*DM + nbase + ncol] = w;
                amax = fmaxf(amax, fmaxf(fabsf(v0), fabsf(v1)));
            }
        }
      }
    }
    if (mode==3){
        for (int off=16;off;off>>=1) amax = fmaxf(amax, __shfl_xor_sync(0xffffffffu, amax, off));
        if (lane==0) red8[wid] = amax;
        __syncthreads();
        if (tid==0){
            float m = red8[0];
            #pragma unroll
            for (int i=1;i<8;i++) m = fmaxf(m, red8[i]);
            atomicMax(&g_absmax, __float_as_int(m));
        }
    }
}

// ---------------- 4a. gather K -> [bh][j][d] bf16 hi/lo ----------------
__global__ void gather_k_kernel()
{
    int idx = blockIdx.x*256 + threadIdx.x;  // 4M
    int d  = idx & 63;
    int j  = (idx>>6) & (TS-1);
    int bh = idx >> 18;
    int b  = bh >> 3;
    if (j < g_cnt[b]){
        int src = g_kept[b*TS + j];
        float kv = g_k[(bh*TS + src)*DHD + d];
        __nv_bfloat16 h = __float2bfloat16(kv);
        g_kchi[idx] = h;
        g_kclo[idx] = __float2bfloat16(kv - __bfloat162float(h));
    }
}
// ---------------- 4b. gather V TRANSPOSED -> [bh][d][j] bf16 hi/lo ----------------
__global__ void gather_v_kernel()
{
    int idx = blockIdx.x*256 + threadIdx.x;  // 4M ; idx = ((bh*64+d)*4096+j)
    int j  = idx & (TS-1);
    int d  = (idx>>12) & 63;
    int bh = idx >> 18;
    int b  = bh >> 3;
    if (j < g_cnt[b]){
        int src = g_kept[b*TS + j];
        float vv = g_v[(bh*TS + src)*DHD + d];
        __nv_bfloat16 h = __float2bfloat16(vv);
        g_vchi[idx] = h;
        g_vclo[idx] = __float2bfloat16(vv - __bfloat162float(h));
    }
}

// ---------------- 5. flash attention via mma (BQ=64, BK=64, dh=64, 128 thr) ----------------
// Direct-LDS fragments (hardware-validated mapping): g=lane>>2, t=lane&3.
#define ASK 144                 // row stride in BYTES (72 bf16)
#define ATT_SMEM (6*64*ASK)     // 55296
__global__ void __launch_bounds__(128) attn_mma_kernel()
{
    extern __shared__ __align__(16) char smem[];
    const int OQH=0, OQL=9216, OKH=18432, OKL=27648, OVH=36864, OVL=46080;
    int bh = blockIdx.y;
    int b = bh>>3, h = bh&7;
    int qbase = blockIdx.x*64;
    int tid = threadIdx.x, lane = tid&31, wid = tid>>5;
    int g = lane>>2, t = lane&3;
    int cnt = g_cnt[b];

    // Q: load fp32, scale by 1/sqrt(dh), hi/lo split into smem
    #pragma unroll
    for (int i=0;i<8;i++){
        int id = tid + i*128;       // 0..1023
        int q = id>>4, c = id&15;   // c = float4 chunk
        float4 v = *(const float4*)&g_q[(bh*TS + qbase + q)*DHD + c*4];
        v.x *= 0.125f; v.y *= 0.125f; v.z *= 0.125f; v.w *= 0.125f;
        __nv_bfloat16 h0=__float2bfloat16(v.x), h1=__float2bfloat16(v.y);
        __nv_bfloat16 h2=__float2bfloat16(v.z), h3=__float2bfloat16(v.w);
        uint32_t hp0 = pkbf(__bfloat162float(h0), __bfloat162float(h1));
        uint32_t hp1 = pkbf(__bfloat162float(h2), __bfloat162float(h3));
        uint32_t lp0 = pkbf(v.x-__bfloat162float(h0), v.y-__bfloat162float(h1));
        uint32_t lp1 = pkbf(v.z-__bfloat162float(h2), v.w-__bfloat162float(h3));
        int o = q*ASK + c*8;
        *(uint32_t*)(smem + OQH + o)     = hp0;
        *(uint32_t*)(smem + OQH + o + 4) = hp1;
        *(uint32_t*)(smem + OQL + o)     = lp0;
        *(uint32_t*)(smem + OQL + o + 4) = lp1;
    }
    __syncthreads();

    // hoist Q fragments (constant across key loop)
    uint32_t qh[4][4], ql[4][4];
    int m0 = wid*16;
    #pragma unroll
    for (int kt=0;kt<4;kt++){
        int k0 = kt*16;
        qh[kt][0] = lds32(smem + OQH + (m0+g  )*ASK + (k0+2*t  )*2);
        qh[kt][1] = lds32(smem + OQH + (m0+g+8)*ASK + (k0+2*t  )*2);
        qh[kt][2] = lds32(smem + OQH + (m0+g  )*ASK + (k0+2*t+8)*2);
        qh[kt][3] = lds32(smem + OQH + (m0+g+8)*ASK + (k0+2*t+8)*2);
        ql[kt][0] = lds32(smem + OQL + (m0+g  )*ASK + (k0+2*t  )*2);
        ql[kt][1] = lds32(smem + OQL + (m0+g+8)*ASK + (k0+2*t  )*2);
        ql[kt][2] = lds32(smem + OQL + (m0+g  )*ASK + (k0+2*t+8)*2);
        ql[kt][3] = lds32(smem + OQL + (m0+g+8)*ASK + (k0+2*t+8)*2);
    }

    float oacc[8][4];
    #pragma unroll
    for (int np=0;np<8;np++){ oacc[np][0]=0.f; oacc[np][1]=0.f; oacc[np][2]=0.f; oacc[np][3]=0.f; }
    float sprev[2] = {-1e30f, -1e30f};
    float lrun[2]  = {0.f, 0.f};

    for (int kb=0; kb<cnt; kb+=64){
        __syncthreads();   // previous iter's K/V smem reads complete
        // K tile: [j][d] rows, hi/lo
        #pragma unroll
        for (int i=0;i<4;i++){
            int id = tid + i*128;   // 0..511
            int j = id>>3, c = id&7;
            int jj = kb + j;
            uint4 z; z.x=0; z.y=0; z.z=0; z.w=0;
            bool ok = jj < cnt;
            uint4 kh = ok ? *(const uint4*)&g_kchi[(bh*TS + jj)*DHD + c*8] : z;
            uint4 kl = ok ? *(const uint4*)&g_kclo[(bh*TS + jj)*DHD + c*8] : z;
            *(uint4*)(smem + OKH + j*ASK + c*16) = kh;
            *(uint4*)(smem + OKL + j*ASK + c*16) = kl;
        }
        // V tile (gmem already transposed): [d][j] rows, hi/lo
        #pragma unroll
        for (int i=0;i<4;i++){
            int id = tid + i*128;
            int d = id>>3, c = id&7;
            int j0 = kb + c*8;
            if (j0 + 8 <= cnt){
                *(uint4*)(smem + OVH + d*ASK + c*16) = *(const uint4*)&g_vchi[(bh*DHD + d)*TS + j0];
                *(uint4*)(smem + OVL + d*ASK + c*16) = *(const uint4*)&g_vclo[(bh*DHD + d)*TS + j0];
            } else {
                #pragma unroll
                for (int e=0;e<8;e++){
                    int jj = j0 + e;
                    __nv_bfloat16 vh = __float2bfloat16(0.f), vl = vh;
                    if (jj < cnt){
                        vh = g_vchi[(bh*DHD + d)*TS + jj];
                        vl = g_vclo[(bh*DHD + d)*TS + jj];
                    }
                    *(__nv_bfloat16*)(smem + OVH + d*ASK + (c*8+e)*2) = vh;
                    *(__nv_bfloat16*)(smem + OVL + d*ASK + (c*8+e)*2) = vl;
                }
            }
        }
        __syncthreads();

        // S = Q K^T (3 hi/lo combos), per-warp m16 x n64 x k64
        float sacc[8][4];
        #pragma unroll
        for (int np=0;np<8;np++){ sacc[np][0]=0.f; sacc[np][1]=0.f; sacc[np][2]=0.f; sacc[np][3]=0.f; }
        #pragma unroll
        for (int kt=0;kt<4;kt++){
            int k0 = kt*16;
            #pragma unroll
            for (int np=0;np<8;np++){
                int nn = np*8 + g;
                uint32_t bh2[2], bl2[2];
                bh2[0] = lds32(smem + OKH + nn*ASK + (k0+2*t  )*2);
                bh2[1] = lds32(smem + OKH + nn*ASK + (k0+2*t+8)*2);
                bl2[0] = lds32(smem + OKL + nn*ASK + (k0+2*t  )*2);
                bl2[1] = lds32(smem + OKL + nn*ASK + (k0+2*t+8)*2);
                mma16816(sacc[np], qh[kt], bh2);
                mma16816(sacc[np], qh[kt], bl2);
                mma16816(sacc[np], ql[kt], bh2);
            }
        }
        // tail mask
        if (kb + 64 > cnt){
            #pragma unroll
            for (int np=0;np<8;np++)
              #pragma unroll
              for (int c=0;c<4;c++){
                  int j = kb + np*8 + 2*t + (c&1);
                  if (j >= cnt) sacc[np][c] = -1e30f;
              }
        }
        // online softmax; rows r0=g (c0,c1), r1=g+8 (c2,c3); 4 t-threads share a row
        float mt0 = sprev[0], mt1 = sprev[1];
        #pragma unroll
        for (int np=0;np<8;np++){
            mt0 = fmaxf(mt0, fmaxf(sacc[np][0], sacc[np][1]));
            mt1 = fmaxf(mt1, fmaxf(sacc[np][2], sacc[np][3]));
        }
        mt0 = fmaxf(mt0, __shfl_xor_sync(0xffffffffu, mt0, 1));
        mt0 = fmaxf(mt0, __shfl_xor_sync(0xffffffffu, mt0, 2));
        mt1 = fmaxf(mt1, __shfl_xor_sync(0xffffffffu, mt1, 1));
        mt1 = fmaxf(mt1, __shfl_xor_sync(0xffffffffu, mt1, 2));
        float c0 = __expf(sprev[0]-mt0), c1 = __expf(sprev[1]-mt1);
        float rs0 = 0.f, rs1 = 0.f;
        #pragma unroll
        for (int np=0;np<8;np++){
            sacc[np][0] = __expf(sacc[np][0]-mt0); rs0 += sacc[np][0];
            sacc[np][1] = __expf(sacc[np][1]-mt0); rs0 += sacc[np][1];
            sacc[np][2] = __expf(sacc[np][2]-mt1); rs1 += sacc[np][2];
            sacc[np][3] = __expf(sacc[np][3]-mt1); rs1 += sacc[np][3];
        }
        rs0 += __shfl_xor_sync(0xffffffffu, rs0, 1);
        rs0 += __shfl_xor_sync(0xffffffffu, rs0, 2);
        rs1 += __shfl_xor_sync(0xffffffffu, rs1, 1);
        rs1 += __shfl_xor_sync(0xffffffffu, rs1, 2);
        lrun[0] = lrun[0]*c0 + rs0;
        lrun[1] = lrun[1]*c1 + rs1;
        sprev[0] = mt0; sprev[1] = mt1;
        #pragma unroll
        for (int np=0;np<8;np++){
            oacc[np][0]*=c0; oacc[np][1]*=c0; oacc[np][2]*=c1; oacc[np][3]*=c1;
        }
        // O += P V (3 combos); P A-frags built in-register (C-layout == A-layout)
        #pragma unroll
        for (int kt=0;kt<4;kt++){
            int k0 = kt*16;
            uint32_t ah[4], al[4];
            {
                float p0 = sacc[2*kt][0],   p1 = sacc[2*kt][1];
                float p2 = sacc[2*kt][2],   p3 = sacc[2*kt][3];
                float p4 = sacc[2*kt+1][0], p5 = sacc[2*kt+1][1];
                float p6 = sacc[2*kt+1][2], p7 = sacc[2*kt+1][3];
                ah[0] = pkbf(p0,p1); ah[1] = pkbf(p2,p3);
                ah[2] = pkbf(p4,p5); ah[3] = pkbf(p6,p7);
                al[0] = pkbf(p0-__bfloat162float(__float2bfloat16(p0)), p1-__bfloat162float(__float2bfloat16(p1)));
                al[1] = pkbf(p2-__bfloat162float(__float2bfloat16(p2)), p3-__bfloat162float(__float2bfloat16(p3)));
                al[2] = pkbf(p4-__bfloat162float(__float2bfloat16(p4)), p5-__bfloat162float(__float2bfloat16(p5)));
                al[3] = pkbf(p6-__bfloat162float(__float2bfloat16(p6)), p7-__bfloat162float(__float2bfloat16(p7)));
            }
            #pragma unroll
            for (int np=0;np<8;np++){
                int nn = np*8 + g;
                uint32_t vh2[2], vl2[2];
                vh2[0] = lds32(smem + OVH + nn*ASK + (k0+2*t  )*2);
                vh2[1] = lds32(smem + OVH + nn*ASK + (k0+2*t+8)*2);
                vl2[0] = lds32(smem + OVL + nn*ASK + (k0+2*t  )*2);
                vl2[1] = lds32(smem + OVL + nn*ASK + (k0+2*t+8)*2);
                mma16816(oacc[np], ah, vh2);
                mma16816(oacc[np], ah, vl2);
                mma16816(oacc[np], al, vh2);
            }
        }
    }
    // epilogue: normalize, hi/lo split, write ctx as bf16 directly
    float inv0 = __fdiv_rn(1.0f, lrun[0]);
    float inv1 = __fdiv_rn(1.0f, lrun[1]);
    int t0 = qbase + m0 + g;
    int t1 = t0 + 8;
    #pragma unroll
    for (int np=0;np<8;np++){
        int col = h*DHD + np*8 + 2*t;
        float v0 = oacc[np][0]*inv0, v1 = oacc[np][1]*inv0;
        float v2 = oacc[np][2]*inv1, v3 = oacc[np][3]*inv1;
        __nv_bfloat16 h0=__float2bfloat16(v0), h1=__float2bfloat16(v1);
        __nv_bfloat16 h2=__float2bfloat16(v2), h3=__float2bfloat16(v3);
        *(uint32_t*)&g_chi[(b*TS + t0)*DM + col] = pkbf(__bfloat162float(h0), __bfloat162float(h1));
        *(uint32_t*)&g_clo[(b*TS + t0)*DM + col] = pkbf(v0-__bfloat162float(h0), v1-__bfloat162float(h1));
        *(uint32_t*)&g_chi[(b*TS + t1)*DM + col] = pkbf(__bfloat162float(h2), __bfloat162float(h3));
        *(uint32_t*)&g_clo[(b*TS + t1)*DM + col] = pkbf(v2-__bfloat162float(h2), v3-__bfloat162float(h3));
    }
}

// ---------------- 7. final per-tensor int8 quant-dequant ----------------
__global__ void quant_out_kernel(float* __restrict__ outp)
{
    float s = fmaxf(__fdiv_rn(__int_as_float(g_absmax), 127.0f), 1e-8f);
    int i = blockIdx.x*256 + threadIdx.x;
    float v = outp[i];
    float qv = rintf(__fdiv_rn(v, s));
    qv = fminf(fmaxf(qv, -127.f), 127.f);
    outp[i] = qv * s;
}

// ---------------- launch ----------------
extern "C" void kernel_launch(void* const* d_in, const int* in_sizes, int n_in,
                              void* d_out, int out_size)
{
    (void)in_sizes; (void)n_in; (void)out_size;
    const float* x  = (const float*)d_in[0];
    const int*   mk = (const int*)  d_in[1];
    const float* Wq = (const float*)d_in[2];
    const float* bq = (const float*)d_in[3];
    const float* Wk = (const float*)d_in[4];
    const float* bk = (const float*)d_in[5];
    const float* Wv = (const float*)d_in[6];
    const float* bv = (const float*)d_in[7];
    const float* Wo = (const float*)d_in[8];
    const float* bo = (const float*)d_in[9];
    float* outp = (float*)d_out;

    cudaFuncSetAttribute(attn_mma_kernel, cudaFuncAttributeMaxDynamicSharedMemorySize, ATT_SMEM);

    quant_weights_kernel<<<dim3(DM,4), 128>>>(Wq,Wk,Wv,Wo);
    split_x_kernel<<<(BT_*DM)/1024, 256>>>(x);
    compact_kernel<<<NB, 1024>>>(mk);
    gemm_mma_kernel<<<dim3(BT_/128, DM/128, 3), 256>>>(bq,bk,bv,bo, outp, 0);
    gather_k_kernel<<<(BH_*TS*DHD)/256, 256>>>();
    gather_v_kernel<<<(BH_*DHD*TS)/256, 256>>>();
    attn_mma_kernel<<<dim3(TS/64, BH_), 128, ATT_SMEM>>>();
    gemm_mma_kernel<<<dim3(BT_/128, DM/128, 1), 256>>>(bq,bk,bv,bo, outp, 3);
    quant_out_kernel<<<(BT_*DM)/256, 256>>>(outp);
}

// round 10
// speedup vs baseline: 3.4201x; 1.3456x over previous
#include <cuda_runtime.h>
#include <cuda_bf16.h>
#include <math.h>
#include <stdint.h>

typedef unsigned long long ull;

#define DM 512
#define TS 4096
#define NB 2
#define NH 8
#define DHD 64
#define BT_ (NB*TS)    // 8192
#define BH_ (NB*NH)    // 16

// ---------------- device scratch (static, allocation-free) ----------------
// RULE (root cause of R4-R7 failures): these symbols are referenced ONLY
// inside device code. Never pass a __device__ symbol as a kernel argument.
__device__ __nv_bfloat16 g_Wb[4][DM*DM];
__device__ float g_ws[4][DM];
__device__ __nv_bfloat16 g_xhi[BT_*DM];
__device__ __nv_bfloat16 g_xlo[BT_*DM];
__device__ __nv_bfloat16 g_chi[BT_*DM];
__device__ __nv_bfloat16 g_clo[BT_*DM];
__device__ float g_q [BH_*TS*DHD];
__device__ float g_k [BH_*TS*DHD];
__device__ float g_v [BH_*TS*DHD];
__device__ __nv_bfloat16 g_kchi[BH_*TS*DHD];  // compacted K, [bh][j][d]
__device__ __nv_bfloat16 g_kclo[BH_*TS*DHD];
__device__ __nv_bfloat16 g_vchi[BH_*DHD*TS];  // compacted V transposed, [bh][d][j]
__device__ __nv_bfloat16 g_vclo[BH_*DHD*TS];
__device__ int   g_kept[NB*TS];
__device__ int   g_cnt[NB];
__device__ int   g_absmax;

// ---------------- mma / cp.async helpers ----------------
static __device__ __forceinline__ void mma16816(float* d, const uint32_t* a, const uint32_t* b){
    asm volatile("mma.sync.aligned.m16n8k16.row.col.f32.bf16.bf16.f32 "
        "{%0,%1,%2,%3}, {%4,%5,%6,%7}, {%8,%9}, {%0,%1,%2,%3};"
        : "+f"(d[0]),"+f"(d[1]),"+f"(d[2]),"+f"(d[3])
        : "r"(a[0]),"r"(a[1]),"r"(a[2]),"r"(a[3]), "r"(b[0]),"r"(b[1]));
}
static __device__ __forceinline__ uint32_t lds32(const void* p){
    return *(const uint32_t*)p;
}
static __device__ __forceinline__ uint32_t pkbf(float x, float y){
    uint32_t r; asm("cvt.rn.bf16x2.f32 %0, %1, %2;" : "=r"(r) : "f"(y), "f"(x)); return r;
}
static __device__ __forceinline__ uint32_t smem_u32(const void* p){
    uint32_t a;
    asm("{ .reg .u64 t; cvta.to.shared.u64 t, %1; cvt.u32.u64 %0, t; }" : "=r"(a) : "l"(p));
    return a;
}
static __device__ __forceinline__ void cp16(uint32_t dst, const void* src){
    asm volatile("cp.async.ca.shared.global [%0], [%1], 16;" :: "r"(dst), "l"(src) : "memory");
}
static __device__ __forceinline__ void cp16z(uint32_t dst, const void* src, int ssz){
    asm volatile("cp.async.ca.shared.global [%0], [%1], 16, %2;" :: "r"(dst), "l"(src), "r"(ssz) : "memory");
}
#define CP_COMMIT() asm volatile("cp.async.commit_group;" ::: "memory")
#define CP_WAIT1()  asm volatile("cp.async.wait_group 1;" ::: "memory")

// ---------------- 1. per-row symmetric int8 weight quant ----------------
__global__ void quant_weights_kernel(const float* __restrict__ Wq, const float* __restrict__ Wk,
                                     const float* __restrict__ Wv, const float* __restrict__ Wo)
{
    int w = blockIdx.y;
    int row = blockIdx.x;
    const float* srcs[4] = {Wq, Wk, Wv, Wo};
    const float* wr = srcs[w] + row*DM;
    __nv_bfloat16* dst = &g_Wb[w][row*DM];
    int tid = threadIdx.x; // 128
    if (w==0 && row==0 && tid==0) g_absmax = 0;
    float mx = 0.f;
    for (int i=tid;i<DM;i+=128) mx = fmaxf(mx, fabsf(wr[i]));
    for (int off=16;off;off>>=1) mx = fmaxf(mx, __shfl_xor_sync(0xffffffffu, mx, off));
    __shared__ float sm4[4];
    if ((tid&31)==0) sm4[tid>>5] = mx;
    __syncthreads();
    mx = fmaxf(fmaxf(sm4[0],sm4[1]), fmaxf(sm4[2],sm4[3]));
    float s = fmaxf(__fdiv_rn(mx, 127.0f), 1e-8f);
    if (tid==0) g_ws[w][row] = s;
    for (int i=tid;i<DM;i+=128){
        float qv = rintf(__fdiv_rn(wr[i], s));
        qv = fminf(fmaxf(qv, -127.f), 127.f);
        dst[i] = __float2bfloat16(qv);
    }
}

// ---------------- 1b. bf16 hi/lo split of x ----------------
__global__ void split_x_kernel(const float* __restrict__ src)
{
    int i = (blockIdx.x*256 + threadIdx.x)*4;
    float4 v = *(const float4*)&src[i];
    __nv_bfloat16 h0=__float2bfloat16(v.x), h1=__float2bfloat16(v.y);
    __nv_bfloat16 h2=__float2bfloat16(v.z), h3=__float2bfloat16(v.w);
    __nv_bfloat162 hA; hA.x=h0; hA.y=h1;
    __nv_bfloat162 hB; hB.x=h2; hB.y=h3;
    __nv_bfloat162 lA; lA.x=__float2bfloat16(v.x-__bfloat162float(h0)); lA.y=__float2bfloat16(v.y-__bfloat162float(h1));
    __nv_bfloat162 lB; lB.x=__float2bfloat16(v.z-__bfloat162float(h2)); lB.y=__float2bfloat16(v.w-__bfloat162float(h3));
    *(__nv_bfloat162*)&g_xhi[i]   = hA;
    *(__nv_bfloat162*)&g_xhi[i+2] = hB;
    *(__nv_bfloat162*)&g_xlo[i]   = lA;
    *(__nv_bfloat162*)&g_xlo[i+2] = lB;
}

// ---------------- 2. mask compaction ----------------
__global__ void compact_kernel(const int* __restrict__ mask)
{
    int b = blockIdx.x;
    const int* m = mask + b*TS;
    __shared__ int part[1024];
    int tid = threadIdx.x; // 1024
    int base = tid*4;
    int f0 = m[base]!=0, f1 = m[base+1]!=0, f2 = m[base+2]!=0, f3 = m[base+3]!=0;
    int s = f0+f1+f2+f3;
    part[tid] = s;
    __syncthreads();
    for (int off=1; off<1024; off<<=1){
        int v = (tid>=off) ? part[tid-off] : 0;
        __syncthreads();
        part[tid] += v;
        __syncthreads();
    }
    int o = part[tid] - s + b*TS;
    if (f0) g_kept[o++] = base;
    if (f1) g_kept[o++] = base+1;
    if (f2) g_kept[o++] = base+2;
    if (f3) g_kept[o++] = base+3;
    if (tid==1023) g_cnt[b] = part[1023];
}

// ---------------- 3. mma GEMM, cp.async 2-stage pipeline ----------------
// Block 128x128, BK=32, 256 threads = 8 warps. Dynamic smem: 2 stages x
// (Ahi|Alo|B) tiles of 128 rows x 80B (40 bf16, 16B-aligned rows).
#define GTILE 10240
#define GST3  (3*GTILE)          // 30720 per stage
#define GEMM_SMEM (2*GST3)       // 61440
__global__ void __launch_bounds__(256) gemm_mma_kernel(
    const float* __restrict__ bq, const float* __restrict__ bk,
    const float* __restrict__ bv, const float* __restrict__ bo,
    float* __restrict__ outp, int modebase)
{
    extern __shared__ __align__(16) char dsm[];
    __shared__ float s_sc[128], s_bi[128];
    __shared__ float red8[8];
    int mode = modebase + blockIdx.z;
    int tid = threadIdx.x, lane = tid&31, wid = tid>>5;
    int wm = wid>>1, wn = wid&1;
    int g = lane>>2, t = lane&3;
    int rowbase = blockIdx.x*128, nbase = blockIdx.y*128;
    uint32_t sbase = smem_u32(dsm);

    const __nv_bfloat16* __restrict__ Ahi = (mode<3) ? g_xhi : g_chi;
    const __nv_bfloat16* __restrict__ Alo = (mode<3) ? g_xlo : g_clo;
    const __nv_bfloat16* __restrict__ Bw  = g_Wb[mode];
    const float* biasp = (mode==0)?bq:((mode==1)?bk:((mode==2)?bv:bo));

    // issue one k-tile into stage st
    auto issue_tile = [&](int st, int kt){
        uint32_t stg = sbase + st*GST3;
        int kb = kt*32;
        #pragma unroll
        for (int i=0;i<2;i++){
            int id = tid + i*256;   // 0..511
            int r = id>>2, c = id&3;
            cp16(stg +           r*80 + c*16, &Ahi[(rowbase+r)*DM + kb + c*8]);
            cp16(stg + GTILE   + r*80 + c*16, &Alo[(rowbase+r)*DM + kb + c*8]);
            cp16(stg + 2*GTILE + r*80 + c*16, &Bw [(nbase  +r)*DM + kb + c*8]);
        }
    };

    issue_tile(0, 0);
    CP_COMMIT();
    if (tid<128) s_sc[tid] = g_ws[mode][nbase+tid];
    else         s_bi[tid-128] = biasp[nbase+tid-128];

    float acc[2][8][4];
    #pragma unroll
    for (int mt=0;mt<2;mt++)
      #pragma unroll
      for (int nt=0;nt<8;nt++)
        #pragma unroll
        for (int c=0;c<4;c++) acc[mt][nt][c] = 0.f;

    for (int kt=0; kt<16; kt++){
        if (kt+1 < 16) issue_tile((kt+1)&1, kt+1);
        CP_COMMIT();
        CP_WAIT1();
        __syncthreads();
        const char* stg = dsm + (kt&1)*GST3;
        #pragma unroll
        for (int ks=0; ks<32; ks+=16){
            uint32_t af[2][2][4];
            #pragma unroll
            for (int h=0; h<2; h++)
              #pragma unroll
              for (int mt=0; mt<2; mt++){
                int r0 = wm*32 + mt*16;
                const char* base = stg + h*GTILE;
                af[h][mt][0] = lds32(base + (r0+g  )*80 + (ks+2*t  )*2);
                af[h][mt][1] = lds32(base + (r0+g+8)*80 + (ks+2*t  )*2);
                af[h][mt][2] = lds32(base + (r0+g  )*80 + (ks+2*t+8)*2);
                af[h][mt][3] = lds32(base + (r0+g+8)*80 + (ks+2*t+8)*2);
              }
            #pragma unroll
            for (int np=0; np<8; np++){
                int n0 = wn*64 + np*8;
                uint32_t bf2[2];
                bf2[0] = lds32(stg + 2*GTILE + (n0+g)*80 + (ks+2*t  )*2);
                bf2[1] = lds32(stg + 2*GTILE + (n0+g)*80 + (ks+2*t+8)*2);
                #pragma unroll
                for (int mt=0; mt<2; mt++){
                    mma16816(acc[mt][np], af[0][mt], bf2);
                    mma16816(acc[mt][np], af[1][mt], bf2);
                }
            }
        }
        __syncthreads();
    }
    float amax = 0.f;
    float* qkv = (mode==0)?g_q:((mode==1)?g_k:g_v);
    #pragma unroll
    for (int mt=0;mt<2;mt++){
      #pragma unroll
      for (int nt=0;nt<8;nt++){
        int ncol = wn*64 + nt*8 + 2*t;
        float s0 = s_sc[ncol], s1 = s_sc[ncol+1];
        float b0 = s_bi[ncol], b1 = s_bi[ncol+1];
        #pragma unroll
        for (int rh=0; rh<2; rh++){
            int row = rowbase + wm*32 + mt*16 + g + rh*8;
            float v0 = acc[mt][nt][rh*2  ]*s0 + b0;
            float v1 = acc[mt][nt][rh*2+1]*s1 + b1;
            float2 w; w.x = v0; w.y = v1;
            if (mode<3){
                int o = nbase + ncol;
                int head = o>>6, dh = o&63;
                int bb = row>>12, tt = row&4095;
                *(float2*)&qkv[((bb*NH+head)*TS + tt)*DHD + dh] = w;
            } else {
                *(float2*)&outp[row*DM + nbase + ncol] = w;
                amax = fmaxf(amax, fmaxf(fabsf(v0), fabsf(v1)));
            }
        }
      }
    }
    if (mode==3){
        for (int off=16;off;off>>=1) amax = fmaxf(amax, __shfl_xor_sync(0xffffffffu, amax, off));
        if (lane==0) red8[wid] = amax;
        __syncthreads();
        if (tid==0){
            float m = red8[0];
            #pragma unroll
            for (int i=1;i<8;i++) m = fmaxf(m, red8[i]);
            atomicMax(&g_absmax, __float_as_int(m));
        }
    }
}

// ---------------- 4a. gather K -> [bh][j][d] bf16 hi/lo ----------------
__global__ void gather_k_kernel()
{
    int idx = blockIdx.x*256 + threadIdx.x;
    int d  = idx & 63;
    int j  = (idx>>6) & (TS-1);
    int bh = idx >> 18;
    int b  = bh >> 3;
    if (j < g_cnt[b]){
        int src = g_kept[b*TS + j];
        float kv = g_k[(bh*TS + src)*DHD + d];
        __nv_bfloat16 h = __float2bfloat16(kv);
        g_kchi[idx] = h;
        g_kclo[idx] = __float2bfloat16(kv - __bfloat162float(h));
    }
}
// ---------------- 4b. gather V transposed -> [bh][d][j] bf16 hi/lo ----------------
__global__ void gather_v_kernel()
{
    int idx = blockIdx.x*256 + threadIdx.x;
    int j  = idx & (TS-1);
    int d  = (idx>>12) & 63;
    int bh = idx >> 18;
    int b  = bh >> 3;
    if (j < g_cnt[b]){
        int src = g_kept[b*TS + j];
        float vv = g_v[(bh*TS + src)*DHD + d];
        __nv_bfloat16 h = __float2bfloat16(vv);
        g_vchi[idx] = h;
        g_vclo[idx] = __float2bfloat16(vv - __bfloat162float(h));
    }
}

// ---------------- 5. flash attention: BQ=128, BK=64, 8 warps, cp.async K/V pipeline ----------
#define ASK 144                  // row stride bytes (72 bf16; 16B aligned)
#define AQ_REG 18432             // Q hi or lo: 128 rows x 144B
#define AST   36864              // per KV stage: KH|KL|VH|VL, 64x144 each
#define ATT_SMEM (2*AQ_REG + 2*AST)   // 110592
__global__ void __launch_bounds__(256, 2) attn_mma_kernel()
{
    extern __shared__ __align__(16) char smem[];
    const int OQH=0, OQL=AQ_REG;
    int bh = blockIdx.y;
    int b = bh>>3, h = bh&7;
    int qbase = blockIdx.x*128;
    int tid = threadIdx.x, lane = tid&31, wid = tid>>5;
    int g = lane>>2, t = lane&3;
    int cnt = g_cnt[b];
    uint32_t sbase = smem_u32(smem);

    // issue K/V tile (64 keys at kb) into stage st; hw zero-fill past cnt
    auto issue_kv = [&](int st, int kb){
        uint32_t stg = sbase + 2*AQ_REG + st*AST;
        #pragma unroll
        for (int i=0;i<2;i++){
            int id = tid + i*256;   // 0..511
            int j = id>>3, c = id&7;
            int jj = kb + j;
            int kssz = (jj < cnt) ? 16 : 0;
            cp16z(stg +         j*ASK + c*16, &g_kchi[(bh*TS+jj)*DHD + c*8], kssz);
            cp16z(stg +  9216 + j*ASK + c*16, &g_kclo[(bh*TS+jj)*DHD + c*8], kssz);
            int vb = (cnt - (kb + c*8))*2;
            vb = vb < 0 ? 0 : (vb > 16 ? 16 : vb);
            cp16z(stg + 18432 + j*ASK + c*16, &g_vchi[(bh*DHD+j)*TS + kb + c*8], vb);
            cp16z(stg + 27648 + j*ASK + c*16, &g_vclo[(bh*DHD+j)*TS + kb + c*8], vb);
        }
    };

    issue_kv(0, 0);
    CP_COMMIT();

    // Q: load fp32, scale, hi/lo split into smem (128 rows)
    #pragma unroll
    for (int i=0;i<8;i++){
        int id = tid + i*256;       // 0..2047
        int q = id>>4, c = id&15;
        float4 v = *(const float4*)&g_q[(bh*TS + qbase + q)*DHD + c*4];
        v.x *= 0.125f; v.y *= 0.125f; v.z *= 0.125f; v.w *= 0.125f;
        __nv_bfloat16 h0=__float2bfloat16(v.x), h1=__float2bfloat16(v.y);
        __nv_bfloat16 h2=__float2bfloat16(v.z), h3=__float2bfloat16(v.w);
        int o = q*ASK + c*8;
        *(uint32_t*)(smem + OQH + o)     = pkbf(__bfloat162float(h0), __bfloat162float(h1));
        *(uint32_t*)(smem + OQH + o + 4) = pkbf(__bfloat162float(h2), __bfloat162float(h3));
        *(uint32_t*)(smem + OQL + o)     = pkbf(v.x-__bfloat162float(h0), v.y-__bfloat162float(h1));
        *(uint32_t*)(smem + OQL + o + 4) = pkbf(v.z-__bfloat162float(h2), v.w-__bfloat162float(h3));
    }
    __syncthreads();

    // hoist Q fragments
    uint32_t qh[4][4], ql[4][4];
    int m0 = wid*16;
    #pragma unroll
    for (int kt=0;kt<4;kt++){
        int k0 = kt*16;
        qh[kt][0] = lds32(smem + OQH + (m0+g  )*ASK + (k0+2*t  )*2);
        qh[kt][1] = lds32(smem + OQH + (m0+g+8)*ASK + (k0+2*t  )*2);
        qh[kt][2] = lds32(smem + OQH + (m0+g  )*ASK + (k0+2*t+8)*2);
        qh[kt][3] = lds32(smem + OQH + (m0+g+8)*ASK + (k0+2*t+8)*2);
        ql[kt][0] = lds32(smem + OQL + (m0+g  )*ASK + (k0+2*t  )*2);
        ql[kt][1] = lds32(smem + OQL + (m0+g+8)*ASK + (k0+2*t  )*2);
        ql[kt][2] = lds32(smem + OQL + (m0+g  )*ASK + (k0+2*t+8)*2);
        ql[kt][3] = lds32(smem + OQL + (m0+g+8)*ASK + (k0+2*t+8)*2);
    }

    float oacc[8][4];
    #pragma unroll
    for (int np=0;np<8;np++){ oacc[np][0]=0.f; oacc[np][1]=0.f; oacc[np][2]=0.f; oacc[np][3]=0.f; }
    float sprev[2] = {-1e30f, -1e30f};
    float lrun[2]  = {0.f, 0.f};
    int NT = (cnt + 63) >> 6;

    for (int it=0; it<NT; it++){
        int kb = it*64;
        if (it+1 < NT) issue_kv((it+1)&1, kb+64);
        CP_COMMIT();
        CP_WAIT1();
        __syncthreads();
        const char* stg = smem + 2*AQ_REG + (it&1)*AST;
        const char* pKH = stg;
        const char* pKL = stg + 9216;
        const char* pVH = stg + 18432;
        const char* pVL = stg + 27648;

        // S = Q K^T (3 hi/lo combos)
        float sacc[8][4];
        #pragma unroll
        for (int np=0;np<8;np++){ sacc[np][0]=0.f; sacc[np][1]=0.f; sacc[np][2]=0.f; sacc[np][3]=0.f; }
        #pragma unroll
        for (int kt=0;kt<4;kt++){
            int k0 = kt*16;
            #pragma unroll
            for (int np=0;np<8;np++){
                int nn = np*8 + g;
                uint32_t bh2[2], bl2[2];
                bh2[0] = lds32(pKH + nn*ASK + (k0+2*t  )*2);
                bh2[1] = lds32(pKH + nn*ASK + (k0+2*t+8)*2);
                bl2[0] = lds32(pKL + nn*ASK + (k0+2*t  )*2);
                bl2[1] = lds32(pKL + nn*ASK + (k0+2*t+8)*2);
                mma16816(sacc[np], qh[kt], bh2);
                mma16816(sacc[np], qh[kt], bl2);
                mma16816(sacc[np], ql[kt], bh2);
            }
        }
        if (kb + 64 > cnt){
            #pragma unroll
            for (int np=0;np<8;np++)
              #pragma unroll
              for (int c=0;c<4;c++){
                  int j = kb + np*8 + 2*t + (c&1);
                  if (j >= cnt) sacc[np][c] = -1e30f;
              }
        }
        // online softmax
        float mt0 = sprev[0], mt1 = sprev[1];
        #pragma unroll
        for (int np=0;np<8;np++){
            mt0 = fmaxf(mt0, fmaxf(sacc[np][0], sacc[np][1]));
            mt1 = fmaxf(mt1, fmaxf(sacc[np][2], sacc[np][3]));
        }
        mt0 = fmaxf(mt0, __shfl_xor_sync(0xffffffffu, mt0, 1));
        mt0 = fmaxf(mt0, __shfl_xor_sync(0xffffffffu, mt0, 2));
        mt1 = fmaxf(mt1, __shfl_xor_sync(0xffffffffu, mt1, 1));
        mt1 = fmaxf(mt1, __shfl_xor_sync(0xffffffffu, mt1, 2));
        float c0 = __expf(sprev[0]-mt0), c1 = __expf(sprev[1]-mt1);
        float rs0 = 0.f, rs1 = 0.f;
        #pragma unroll
        for (int np=0;np<8;np++){
            sacc[np][0] = __expf(sacc[np][0]-mt0); rs0 += sacc[np][0];
            sacc[np][1] = __expf(sacc[np][1]-mt0); rs0 += sacc[np][1];
            sacc[np][2] = __expf(sacc[np][2]-mt1); rs1 += sacc[np][2];
            sacc[np][3] = __expf(sacc[np][3]-mt1); rs1 += sacc[np][3];
        }
        rs0 += __shfl_xor_sync(0xffffffffu, rs0, 1);
        rs0 += __shfl_xor_sync(0xffffffffu, rs0, 2);
        rs1 += __shfl_xor_sync(0xffffffffu, rs1, 1);
        rs1 += __shfl_xor_sync(0xffffffffu, rs1, 2);
        lrun[0] = lrun[0]*c0 + rs0;
        lrun[1] = lrun[1]*c1 + rs1;
        sprev[0] = mt0; sprev[1] = mt1;
        #pragma unroll
        for (int np=0;np<8;np++){
            oacc[np][0]*=c0; oacc[np][1]*=c0; oacc[np][2]*=c1; oacc[np][3]*=c1;
        }
        // O += P V (3 combos); P A-frags in-register (C-layout == A-layout)
        #pragma unroll
        for (int kt=0;kt<4;kt++){
            int k0 = kt*16;
            uint32_t ah[4], al[4];
            {
                float p0 = sacc[2*kt][0],   p1 = sacc[2*kt][1];
                float p2 = sacc[2*kt][2],   p3 = sacc[2*kt][3];
                float p4 = sacc[2*kt+1][0], p5 = sacc[2*kt+1][1];
                float p6 = sacc[2*kt+1][2], p7 = sacc[2*kt+1][3];
                ah[0] = pkbf(p0,p1); ah[1] = pkbf(p2,p3);
                ah[2] = pkbf(p4,p5); ah[3] = pkbf(p6,p7);
                al[0] = pkbf(p0-__bfloat162float(__float2bfloat16(p0)), p1-__bfloat162float(__float2bfloat16(p1)));
                al[1] = pkbf(p2-__bfloat162float(__float2bfloat16(p2)), p3-__bfloat162float(__float2bfloat16(p3)));
                al[2] = pkbf(p4-__bfloat162float(__float2bfloat16(p4)), p5-__bfloat162float(__float2bfloat16(p5)));
                al[3] = pkbf(p6-__bfloat162float(__float2bfloat16(p6)), p7-__bfloat162float(__float2bfloat16(p7)));
            }
            #pragma unroll
            for (int np=0;np<8;np++){
                int nn = np*8 + g;
                uint32_t vh2[2], vl2[2];
                vh2[0] = lds32(pVH + nn*ASK + (k0+2*t  )*2);
                vh2[1] = lds32(pVH + nn*ASK + (k0+2*t+8)*2);
                vl2[0] = lds32(pVL + nn*ASK + (k0+2*t  )*2);
                vl2[1] = lds32(pVL + nn*ASK + (k0+2*t+8)*2);
                mma16816(oacc[np], ah, vh2);
                mma16816(oacc[np], ah, vl2);
                mma16816(oacc[np], al, vh2);
            }
        }
        __syncthreads();
    }
    // epilogue: normalize, hi/lo split, write ctx as bf16
    float inv0 = __fdiv_rn(1.0f, lrun[0]);
    float inv1 = __fdiv_rn(1.0f, lrun[1]);
    int t0 = qbase + m0 + g;
    int t1 = t0 + 8;
    #pragma unroll
    for (int np=0;np<8;np++){
        int col = h*DHD + np*8 + 2*t;
        float v0 = oacc[np][0]*inv0, v1 = oacc[np][1]*inv0;
        float v2 = oacc[np][2]*inv1, v3 = oacc[np][3]*inv1;
        __nv_bfloat16 h0=__float2bfloat16(v0), h1=__float2bfloat16(v1);
        __nv_bfloat16 h2=__float2bfloat16(v2), h3=__float2bfloat16(v3);
        *(uint32_t*)&g_chi[(b*TS + t0)*DM + col] = pkbf(__bfloat162float(h0), __bfloat162float(h1));
        *(uint32_t*)&g_clo[(b*TS + t0)*DM + col] = pkbf(v0-__bfloat162float(h0), v1-__bfloat162float(h1));
        *(uint32_t*)&g_chi[(b*TS + t1)*DM + col] = pkbf(__bfloat162float(h2), __bfloat162float(h3));
        *(uint32_t*)&g_clo[(b*TS + t1)*DM + col] = pkbf(v2-__bfloat162float(h2), v3-__bfloat162float(h3));
    }
}

// ---------------- 7. final per-tensor int8 quant-dequant ----------------
__global__ void quant_out_kernel(float* __restrict__ outp)
{
    float s = fmaxf(__fdiv_rn(__int_as_float(g_absmax), 127.0f), 1e-8f);
    int i = blockIdx.x*256 + threadIdx.x;
    float v = outp[i];
    float qv = rintf(__fdiv_rn(v, s));
    qv = fminf(fmaxf(qv, -127.f), 127.f);
    outp[i] = qv * s;
}

// ---------------- launch ----------------
extern "C" void kernel_launch(void* const* d_in, const int* in_sizes, int n_in,
                              void* d_out, int out_size)
{
    (void)in_sizes; (void)n_in; (void)out_size;
    const float* x  = (const float*)d_in[0];
    const int*   mk = (const int*)  d_in[1];
    const float* Wq = (const float*)d_in[2];
    const float* bq = (const float*)d_in[3];
    const float* Wk = (const float*)d_in[4];
    const float* bk = (const float*)d_in[5];
    const float* Wv = (const float*)d_in[6];
    const float* bv = (const float*)d_in[7];
    const float* Wo = (const float*)d_in[8];
    const float* bo = (const float*)d_in[9];
    float* outp = (float*)d_out;

    cudaFuncSetAttribute(gemm_mma_kernel, cudaFuncAttributeMaxDynamicSharedMemorySize, GEMM_SMEM);
    cudaFuncSetAttribute(attn_mma_kernel, cudaFuncAttributeMaxDynamicSharedMemorySize, ATT_SMEM);

    quant_weights_kernel<<<dim3(DM,4), 128>>>(Wq,Wk,Wv,Wo);
    split_x_kernel<<<(BT_*DM)/1024, 256>>>(x);
    compact_kernel<<<NB, 1024>>>(mk);
    gemm_mma_kernel<<<dim3(BT_/128, DM/128, 3), 256, GEMM_SMEM>>>(bq,bk,bv,bo, outp, 0);
    gather_k_kernel<<<(BH_*TS*DHD)/256, 256>>>();
    gather_v_kernel<<<(BH_*DHD*TS)/256, 256>>>();
    attn_mma_kernel<<<dim3(TS/128, BH_), 256, ATT_SMEM>>>();
    gemm_mma_kernel<<<dim3(BT_/128, DM/128, 1), 256, GEMM_SMEM>>>(bq,bk,bv,bo, outp, 3);
    quant_out_kernel<<<(BT_*DM)/256, 256>>>(outp);
}